// round 14
// baseline (speedup 1.0000x reference)
#include <cuda_runtime.h>
#include <cuda_fp16.h>
#include <cstdint>

// ============================================================================
// ConvAConnect: per-sample perturbed 3x3 SAME conv, B=32 H=W=64 Cin=128 F=256
// R14: R13 (128x128 CTA tile, 4x 64x64 warps, one-time fp16 X halo in smem,
// barrier-free mainloop) with B staged through a 4-deep WARP-LOCAL cp.async
// smem ring (distance 3, wait_group 2) instead of a register double-buffer.
// fp16 m16n8k16, f32 accumulate.
// ============================================================================
static constexpr int BATCH = 32;
static constexpr int CIN   = 128;
static constexpr int FOUT  = 256;
static constexpr int NG16  = 72;    // K=1152 / 16
static constexpr int HROWS = 4 * 66;               // halo rows (yy*66+xx)
static constexpr uint32_t HALO_BYTES = 264 * 256;  // 67584
static constexpr uint32_t RING_OFF   = HALO_BYTES; // 4 slots x 8KB
static constexpr uint32_t RING_BYTES = 4 * 8192;
static constexpr uint32_t SMEM_MB    = RING_OFF + RING_BYTES;   // 100352
static constexpr uint32_t SMEM_TOTAL = SMEM_MB + 512;           // 100864

// fp16 per-sample weights in exact m16n8k16 B-fragment order (same as R5-R13):
// half index = ((b*72 + g)*4 + wnq)*1024 + q*256 + lane*8 + e*4 + r*2 + p
__device__ __align__(256) __half g_wfrag[(size_t)BATCH * NG16 * 4096];

__device__ __forceinline__ uint32_t smem_u32(const void* p) {
    uint32_t a;
    asm("{ .reg .u64 t; cvta.to.shared.u64 t, %1; cvt.u32.u64 %0, t; }" : "=r"(a) : "l"(p));
    return a;
}
// 3-bit row-rotation swizzle on the 16B-segment index (conflict-free for
// LDSM octets over consecutive rows and for halo-fill STS).
__device__ __forceinline__ uint32_t swz3(uint32_t r) {
    return ((r & 1u) << 2) | ((r >> 1) & 3u);
}

// ============================================================================
// Prep: g_wfrag = frag_order(f16(W * Werr[b])). One block per (b, pos).
// ============================================================================
__global__ void __launch_bounds__(256) prep_wfrag(const float* __restrict__ W,
                                                  const float* __restrict__ Werr) {
    __shared__ float4 st4[512];                    // 8KB = 4096 halves
    __half* st = (__half*)st4;
    int blk = blockIdx.x;
    int b = blk / 9, pos = blk % 9;
    int f = threadIdx.x;                           // 0..255
    const float* wb = W    + (size_t)pos * CIN * FOUT + f;
    const float* eb = Werr + (size_t)(b * 9 + pos) * CIN * FOUT + f;
    const int wn = f >> 6, q = (f >> 4) & 3, e = (f >> 3) & 1;
    const int lane_base = (f & 7) * 4;

    for (int slab = 0; slab < 8; slab++) {         // 16 channels each
        __syncthreads();
#pragma unroll
        for (int ci = 0; ci < 16; ci++) {
            int c = slab * 16 + ci;
            float v = wb[(size_t)c * FOUT] * eb[(size_t)c * FOUT];
            int lane = lane_base + ((ci & 7) >> 1);
            int r = ci >> 3, p = ci & 1;
            st[wn * 1024 + q * 256 + lane * 8 + e * 4 + r * 2 + p] = __float2half_rn(v);
        }
        __syncthreads();
        int g = pos * 8 + slab;
        float4* dst = (float4*)(g_wfrag + (size_t)(b * NG16 + g) * 4096);
        dst[f * 2]     = st4[f * 2];
        dst[f * 2 + 1] = st4[f * 2 + 1];
    }
}

// ============================================================================
// Main: 2048 CTAs = 32 b x 32 mb (128 px = 2 image rows) x 2 nb (128 f).
// 128 threads, 4 warps: wm = wid>>1 (64-px M half), wn = wid&1 (64-f half).
// ============================================================================
__global__ void __launch_bounds__(128, 2)
conv_main(const float* __restrict__ X, const float* __restrict__ bias,
          const float* __restrict__ Berr, float* __restrict__ out) {
    extern __shared__ char smem[];
    const uint32_t sA = smem_u32(smem);
    float* sMB = (float*)(smem + SMEM_MB);

    const int t = threadIdx.x, l = t & 31, wid = t >> 5;
    const int b  = blockIdx.x >> 6;
    const int mb = (blockIdx.x >> 1) & 31;
    const int nb = blockIdx.x & 1;
    const int wm = wid >> 1, wn = wid & 1;

    sMB[t] = bias[nb * 128 + t] * Berr[b * FOUT + nb * 128 + t];

    // ---- one-time X halo fill: rows r = yy*66+xx, fp16, zero-padded ----
    for (int r = wid; r < HROWS; r += 4) {
        int yy = r / 66, xx = r - yy * 66;
        int y = mb * 2 - 1 + yy, x = xx - 1;
        bool valid = ((unsigned)y < 64u) && ((unsigned)x < 64u);
        float4 v = make_float4(0.f, 0.f, 0.f, 0.f);
        if (valid)
            v = ((const float4*)(X + (((size_t)b * 64 + y) * 64 + x) * CIN))[l];
        uint32_t h0, h1;
        asm volatile("cvt.rn.f16x2.f32 %0, %1, %2;" : "=r"(h0) : "f"(v.y), "f"(v.x));
        asm volatile("cvt.rn.f16x2.f32 %0, %1, %2;" : "=r"(h1) : "f"(v.w), "f"(v.z));
        uint32_t seg = (uint32_t)(l >> 1);
        uint32_t d = sA + (uint32_t)r * 256u + ((seg ^ swz3((uint32_t)r)) * 16u) +
                     (uint32_t)((l & 1) * 8);
        asm volatile("st.shared.v2.b32 [%0], {%1,%2};" :: "r"(d), "r"(h0), "r"(h1)
                     : "memory");
    }

    // ---- consumer ldmatrix lane addressing ----
    const int lm = l >> 3, lri = l & 7;
    const uint32_t segHi = (uint32_t)(lm >> 1);       // 0: k0-7, 1: k8-15
    int xb[4];                                        // x-offset per mt
#pragma unroll
    for (int mt = 0; mt < 4; mt++) xb[mt] = mt * 16 + lri + (lm & 1) * 8;

    // ---- B ring: warp-local slab, cp.async distance 3, 4 slots ----
    const int wnq = nb * 2 + wn;                      // global f quarter
    const uint4* bp = (const uint4*)g_wfrag +
                      (size_t)b * NG16 * 512 + wnq * 128 + l;
    const uint32_t ringBase = sA + RING_OFF + (uint32_t)wid * 2048u +
                              (uint32_t)l * 16u;

    auto issueB = [&](int gfetch, int slot) {
        const uint4* src = bp + (size_t)gfetch * 512;
        uint32_t d = ringBase + (uint32_t)slot * 8192u;
#pragma unroll
        for (int qq = 0; qq < 4; qq++) {
            asm volatile("cp.async.cg.shared.global [%0], [%1], 16;"
                         :: "r"(d + (uint32_t)qq * 512u), "l"(src + qq * 32)
                         : "memory");
        }
        asm volatile("cp.async.commit_group;" ::: "memory");
    };

    float acc[4][8][4];
#pragma unroll
    for (int mt = 0; mt < 4; mt++)
#pragma unroll
        for (int nt = 0; nt < 8; nt++)
#pragma unroll
            for (int qq = 0; qq < 4; qq++) acc[mt][nt][qq] = 0.f;

    // B prologue: slots for g = 0, 1, 2 (3 outstanding groups)
    issueB(0, 0);
    issueB(1, 1);
    issueB(2, 2);
    __syncthreads();    // halo visible to all warps

    // ---- barrier-free mainloop: 9 positions x 8 k16 ----
    for (int s = 0; s < 9; s++) {
        int kh = s / 3, kw = s - kh * 3;
        const int rowoff = (wm + kh) * 66 + kw;       // smem halo row base

#pragma unroll
        for (int kk = 0; kk < 8; kk++) {
            int g = s * 8 + kk;

            // wait until slot g is ready (<=2 newer groups outstanding)
            asm volatile("cp.async.wait_group 2;" ::: "memory");

            // B fragments: 4 conflict-free LDS.128 from this warp's slab
            uint4 bq[4];
            const uint32_t sb = ringBase + (uint32_t)(g & 3) * 8192u;
#pragma unroll
            for (int qq = 0; qq < 4; qq++) {
                asm volatile("ld.shared.v4.b32 {%0,%1,%2,%3}, [%4];"
                             : "=r"(bq[qq].x), "=r"(bq[qq].y),
                               "=r"(bq[qq].z), "=r"(bq[qq].w)
                             : "r"(sb + (uint32_t)qq * 512u));
            }

            // A fragments via ldmatrix.x4 (one per mt) from the halo
            uint32_t a[4][4];
            const uint32_t seg = (uint32_t)(kk * 2) + segHi;
#pragma unroll
            for (int mt = 0; mt < 4; mt++) {
                uint32_t rr = (uint32_t)(rowoff + xb[mt]);
                uint32_t addr = sA + rr * 256u + ((seg ^ swz3(rr)) * 16u);
                asm volatile("ldmatrix.sync.aligned.m8n8.x4.shared.b16 "
                             "{%0,%1,%2,%3}, [%4];"
                             : "=r"(a[mt][0]), "=r"(a[mt][1]),
                               "=r"(a[mt][2]), "=r"(a[mt][3])
                             : "r"(addr));
            }

#pragma unroll
            for (int mt = 0; mt < 4; mt++)
#pragma unroll
                for (int nt = 0; nt < 8; nt++) {
                    const uint4 qv = bq[nt >> 1];
                    uint32_t b0, b1;
                    if (nt & 1) { b0 = qv.z; b1 = qv.w; }
                    else        { b0 = qv.x; b1 = qv.y; }
                    asm volatile(
                        "mma.sync.aligned.m16n8k16.row.col.f32.f16.f16.f32 "
                        "{%0,%1,%2,%3}, {%4,%5,%6,%7}, {%8,%9}, {%0,%1,%2,%3};"
                        : "+f"(acc[mt][nt][0]), "+f"(acc[mt][nt][1]),
                          "+f"(acc[mt][nt][2]), "+f"(acc[mt][nt][3])
                        : "r"(a[mt][0]), "r"(a[mt][1]), "r"(a[mt][2]), "r"(a[mt][3]),
                          "r"(b0), "r"(b1));
                }

            // refill slot (g+3)&3 with slab g+3 (clamped; redundant at tail)
            {
                int gf = (g + 3 < NG16) ? g + 3 : NG16 - 1;
                issueB(gf, (g + 3) & 3);
            }
        }
    }

    // ---- epilogue: bias + relu + float2 stores ----
#pragma unroll
    for (int mt = 0; mt < 4; mt++) {
        int pix = mb * 128 + wm * 64 + mt * 16 + (l >> 2);
        float* o = out + ((size_t)b * 4096 + pix) * FOUT + nb * 128;
#pragma unroll
        for (int nt = 0; nt < 8; nt++) {
            int f0 = wn * 64 + nt * 8 + (l & 3) * 2;
            float m0v = sMB[f0], m1v = sMB[f0 + 1];
            float2 r0, r1;
            r0.x = fmaxf(acc[mt][nt][0] + m0v, 0.f);
            r0.y = fmaxf(acc[mt][nt][1] + m1v, 0.f);
            r1.x = fmaxf(acc[mt][nt][2] + m0v, 0.f);
            r1.y = fmaxf(acc[mt][nt][3] + m1v, 0.f);
            *(float2*)(o + f0) = r0;
            *(float2*)(o + (size_t)8 * FOUT + f0) = r1;
        }
    }
    // drain remaining cp.async groups (writes only smem ring; harmless)
    asm volatile("cp.async.wait_group 0;" ::: "memory");
}

// ============================================================================
// kernel_launch — size-match (elements or bytes) + positional fallback.
// ============================================================================
extern "C" void kernel_launch(void* const* d_in, const int* in_sizes, int n_in,
                              void* d_out, int out_size) {
    const long long EX = 33554432LL, EW = 294912LL, EBI = 256LL,
                    EWE = 9437184LL, EBE = 8192LL;

    auto pick = [&](long long elems) -> const float* {
        for (int i = 0; i < n_in; i++) {
            long long s = (long long)in_sizes[i];
            if (s == elems || s == elems * 4) return (const float*)d_in[i];
        }
        return nullptr;
    };
    const float* X    = pick(EX);
    const float* W    = pick(EW);
    const float* bias = pick(EBI);
    const float* Werr = pick(EWE);
    const float* Berr = pick(EBE);

    if (!X || !W || !bias || !Werr || !Berr) {
        if (n_in >= 5) {
            X    = (const float*)d_in[0];
            W    = (const float*)d_in[1];
            bias = (const float*)d_in[2];
            Werr = (const float*)d_in[3];
            Berr = (const float*)d_in[4];
        } else {
            return;
        }
    }

    float* out = (float*)d_out;

    cudaFuncSetAttribute(conv_main, cudaFuncAttributeMaxDynamicSharedMemorySize,
                         (int)SMEM_TOTAL);

    prep_wfrag<<<BATCH * 9, 256>>>(W, Werr);
    conv_main<<<BATCH * 64, 128, SMEM_TOTAL>>>(X, bias, Berr, out);
}

// round 15
// speedup vs baseline: 1.0087x; 1.0087x over previous
#include <cuda_runtime.h>
#include <cuda_fp16.h>
#include <cstdint>

// ============================================================================
// ConvAConnect: per-sample perturbed 3x3 SAME conv, B=32 H=W=64 Cin=128 F=256
// R15: R14 (128x128 CTA tile, 4x 64x64 warps, fp16 X halo resident in smem,
// warp-local 4-deep cp.async B ring) + software-pipelined A fragments:
// LDSM for kk+1 issued before the MMA block of kk (double-buffered a[2]),
// issueB hoisted ahead of the MMAs. fp16 m16n8k16, f32 accumulate.
// ============================================================================
static constexpr int BATCH = 32;
static constexpr int CIN   = 128;
static constexpr int FOUT  = 256;
static constexpr int NG16  = 72;    // K=1152 / 16
static constexpr int HROWS = 4 * 66;               // halo rows (yy*66+xx)
static constexpr uint32_t HALO_BYTES = 264 * 256;  // 67584
static constexpr uint32_t RING_OFF   = HALO_BYTES; // 4 slots x 8KB
static constexpr uint32_t RING_BYTES = 4 * 8192;
static constexpr uint32_t SMEM_MB    = RING_OFF + RING_BYTES;   // 100352
static constexpr uint32_t SMEM_TOTAL = SMEM_MB + 512;           // 100864

// fp16 per-sample weights in exact m16n8k16 B-fragment order (same as R5-R14):
// half index = ((b*72 + g)*4 + wnq)*1024 + q*256 + lane*8 + e*4 + r*2 + p
__device__ __align__(256) __half g_wfrag[(size_t)BATCH * NG16 * 4096];

__device__ __forceinline__ uint32_t smem_u32(const void* p) {
    uint32_t a;
    asm("{ .reg .u64 t; cvta.to.shared.u64 t, %1; cvt.u32.u64 %0, t; }" : "=r"(a) : "l"(p));
    return a;
}
// 3-bit row-rotation swizzle on the 16B-segment index (conflict-free for
// LDSM octets over consecutive rows and for halo-fill STS).
__device__ __forceinline__ uint32_t swz3(uint32_t r) {
    return ((r & 1u) << 2) | ((r >> 1) & 3u);
}

// ============================================================================
// Prep: g_wfrag = frag_order(f16(W * Werr[b])). One block per (b, pos).
// ============================================================================
__global__ void __launch_bounds__(256) prep_wfrag(const float* __restrict__ W,
                                                  const float* __restrict__ Werr) {
    __shared__ float4 st4[512];                    // 8KB = 4096 halves
    __half* st = (__half*)st4;
    int blk = blockIdx.x;
    int b = blk / 9, pos = blk % 9;
    int f = threadIdx.x;                           // 0..255
    const float* wb = W    + (size_t)pos * CIN * FOUT + f;
    const float* eb = Werr + (size_t)(b * 9 + pos) * CIN * FOUT + f;
    const int wn = f >> 6, q = (f >> 4) & 3, e = (f >> 3) & 1;
    const int lane_base = (f & 7) * 4;

    for (int slab = 0; slab < 8; slab++) {         // 16 channels each
        __syncthreads();
#pragma unroll
        for (int ci = 0; ci < 16; ci++) {
            int c = slab * 16 + ci;
            float v = wb[(size_t)c * FOUT] * eb[(size_t)c * FOUT];
            int lane = lane_base + ((ci & 7) >> 1);
            int r = ci >> 3, p = ci & 1;
            st[wn * 1024 + q * 256 + lane * 8 + e * 4 + r * 2 + p] = __float2half_rn(v);
        }
        __syncthreads();
        int g = pos * 8 + slab;
        float4* dst = (float4*)(g_wfrag + (size_t)(b * NG16 + g) * 4096);
        dst[f * 2]     = st4[f * 2];
        dst[f * 2 + 1] = st4[f * 2 + 1];
    }
}

// ============================================================================
// Main: 2048 CTAs = 32 b x 32 mb (128 px = 2 image rows) x 2 nb (128 f).
// 128 threads, 4 warps: wm = wid>>1 (64-px M half), wn = wid&1 (64-f half).
// ============================================================================
__global__ void __launch_bounds__(128, 2)
conv_main(const float* __restrict__ X, const float* __restrict__ bias,
          const float* __restrict__ Berr, float* __restrict__ out) {
    extern __shared__ char smem[];
    const uint32_t sA = smem_u32(smem);
    float* sMB = (float*)(smem + SMEM_MB);

    const int t = threadIdx.x, l = t & 31, wid = t >> 5;
    const int b  = blockIdx.x >> 6;
    const int mb = (blockIdx.x >> 1) & 31;
    const int nb = blockIdx.x & 1;
    const int wm = wid >> 1, wn = wid & 1;

    sMB[t] = bias[nb * 128 + t] * Berr[b * FOUT + nb * 128 + t];

    // ---- one-time X halo fill: rows r = yy*66+xx, fp16, zero-padded ----
    for (int r = wid; r < HROWS; r += 4) {
        int yy = r / 66, xx = r - yy * 66;
        int y = mb * 2 - 1 + yy, x = xx - 1;
        bool valid = ((unsigned)y < 64u) && ((unsigned)x < 64u);
        float4 v = make_float4(0.f, 0.f, 0.f, 0.f);
        if (valid)
            v = ((const float4*)(X + (((size_t)b * 64 + y) * 64 + x) * CIN))[l];
        uint32_t h0, h1;
        asm volatile("cvt.rn.f16x2.f32 %0, %1, %2;" : "=r"(h0) : "f"(v.y), "f"(v.x));
        asm volatile("cvt.rn.f16x2.f32 %0, %1, %2;" : "=r"(h1) : "f"(v.w), "f"(v.z));
        uint32_t seg = (uint32_t)(l >> 1);
        uint32_t d = sA + (uint32_t)r * 256u + ((seg ^ swz3((uint32_t)r)) * 16u) +
                     (uint32_t)((l & 1) * 8);
        asm volatile("st.shared.v2.b32 [%0], {%1,%2};" :: "r"(d), "r"(h0), "r"(h1)
                     : "memory");
    }

    // ---- consumer ldmatrix lane addressing ----
    const int lm = l >> 3, lri = l & 7;
    const uint32_t segHi = (uint32_t)(lm >> 1);       // 0: k0-7, 1: k8-15
    int xb[4];                                        // x-offset per mt
#pragma unroll
    for (int mt = 0; mt < 4; mt++) xb[mt] = mt * 16 + lri + (lm & 1) * 8;

    // ---- B ring: warp-local slab, cp.async distance 3, 4 slots ----
    const int wnq = nb * 2 + wn;                      // global f quarter
    const uint4* bp = (const uint4*)g_wfrag +
                      (size_t)b * NG16 * 512 + wnq * 128 + l;
    const uint32_t ringBase = sA + RING_OFF + (uint32_t)wid * 2048u +
                              (uint32_t)l * 16u;

    auto issueB = [&](int gfetch, int slot) {
        const uint4* src = bp + (size_t)gfetch * 512;
        uint32_t d = ringBase + (uint32_t)slot * 8192u;
#pragma unroll
        for (int qq = 0; qq < 4; qq++) {
            asm volatile("cp.async.cg.shared.global [%0], [%1], 16;"
                         :: "r"(d + (uint32_t)qq * 512u), "l"(src + qq * 32)
                         : "memory");
        }
        asm volatile("cp.async.commit_group;" ::: "memory");
    };

    // A-fragment double buffer + LDSM issue helper
    uint32_t a[2][4][4];
    auto ldsmA = [&](int buf, int kk, int rowoff) {
        const uint32_t seg = (uint32_t)(kk * 2) + segHi;
#pragma unroll
        for (int mt = 0; mt < 4; mt++) {
            uint32_t rr = (uint32_t)(rowoff + xb[mt]);
            uint32_t addr = sA + rr * 256u + ((seg ^ swz3(rr)) * 16u);
            asm volatile("ldmatrix.sync.aligned.m8n8.x4.shared.b16 "
                         "{%0,%1,%2,%3}, [%4];"
                         : "=r"(a[buf][mt][0]), "=r"(a[buf][mt][1]),
                           "=r"(a[buf][mt][2]), "=r"(a[buf][mt][3])
                         : "r"(addr));
        }
    };

    float acc[4][8][4];
#pragma unroll
    for (int mt = 0; mt < 4; mt++)
#pragma unroll
        for (int nt = 0; nt < 8; nt++)
#pragma unroll
            for (int qq = 0; qq < 4; qq++) acc[mt][nt][qq] = 0.f;

    // B prologue: slots for g = 0, 1, 2 (3 outstanding groups)
    issueB(0, 0);
    issueB(1, 1);
    issueB(2, 2);
    __syncthreads();    // halo visible to all warps

    // A prologue: fragments for s=0, kk=0
    {
        const int rowoff0 = wm * 66;                  // s=0: kh=0, kw=0
        ldsmA(0, 0, rowoff0);
    }

    // ---- barrier-free mainloop: 9 positions x 8 k16 ----
    for (int s = 0; s < 9; s++) {
        int kh = s / 3, kw = s - kh * 3;
        const int rowoff = (wm + kh) * 66 + kw;
        int s1 = (s + 1 < 9) ? s + 1 : 8;
        int kh1 = s1 / 3, kw1 = s1 - kh1 * 3;
        const int rowoffN = (wm + kh1) * 66 + kw1;    // next position's base

#pragma unroll
        for (int kk = 0; kk < 8; kk++) {
            int g = s * 8 + kk;
            const int cur = kk & 1, nxt = cur ^ 1;

            // wait until slot g is ready (<=2 newer groups outstanding)
            asm volatile("cp.async.wait_group 2;" ::: "memory");

            // B fragments: 4 conflict-free LDS.128 from this warp's slab
            uint4 bq[4];
            const uint32_t sb = ringBase + (uint32_t)(g & 3) * 8192u;
#pragma unroll
            for (int qq = 0; qq < 4; qq++) {
                asm volatile("ld.shared.v4.b32 {%0,%1,%2,%3}, [%4];"
                             : "=r"(bq[qq].x), "=r"(bq[qq].y),
                               "=r"(bq[qq].z), "=r"(bq[qq].w)
                             : "r"(sb + (uint32_t)qq * 512u));
            }

            // refill slot (g+3)&3 early (maximize cp.async cover)
            {
                int gf = (g + 3 < NG16) ? g + 3 : NG16 - 1;
                issueB(gf, (g + 3) & 3);
            }

            // prefetch A fragments for the NEXT k16 (hidden under MMAs below)
            if (kk < 7) ldsmA(nxt, kk + 1, rowoff);
            else        ldsmA(nxt, 0, rowoffN);

#pragma unroll
            for (int mt = 0; mt < 4; mt++)
#pragma unroll
                for (int nt = 0; nt < 8; nt++) {
                    const uint4 qv = bq[nt >> 1];
                    uint32_t b0, b1;
                    if (nt & 1) { b0 = qv.z; b1 = qv.w; }
                    else        { b0 = qv.x; b1 = qv.y; }
                    asm volatile(
                        "mma.sync.aligned.m16n8k16.row.col.f32.f16.f16.f32 "
                        "{%0,%1,%2,%3}, {%4,%5,%6,%7}, {%8,%9}, {%0,%1,%2,%3};"
                        : "+f"(acc[mt][nt][0]), "+f"(acc[mt][nt][1]),
                          "+f"(acc[mt][nt][2]), "+f"(acc[mt][nt][3])
                        : "r"(a[cur][mt][0]), "r"(a[cur][mt][1]),
                          "r"(a[cur][mt][2]), "r"(a[cur][mt][3]),
                          "r"(b0), "r"(b1));
                }
        }
    }

    // ---- epilogue: bias + relu + float2 stores ----
#pragma unroll
    for (int mt = 0; mt < 4; mt++) {
        int pix = mb * 128 + wm * 64 + mt * 16 + (l >> 2);
        float* o = out + ((size_t)b * 4096 + pix) * FOUT + nb * 128;
#pragma unroll
        for (int nt = 0; nt < 8; nt++) {
            int f0 = wn * 64 + nt * 8 + (l & 3) * 2;
            float m0v = sMB[f0], m1v = sMB[f0 + 1];
            float2 r0, r1;
            r0.x = fmaxf(acc[mt][nt][0] + m0v, 0.f);
            r0.y = fmaxf(acc[mt][nt][1] + m1v, 0.f);
            r1.x = fmaxf(acc[mt][nt][2] + m0v, 0.f);
            r1.y = fmaxf(acc[mt][nt][3] + m1v, 0.f);
            *(float2*)(o + f0) = r0;
            *(float2*)(o + (size_t)8 * FOUT + f0) = r1;
        }
    }
    // drain remaining cp.async groups (writes only smem ring; harmless)
    asm volatile("cp.async.wait_group 0;" ::: "memory");
}

// ============================================================================
// kernel_launch — size-match (elements or bytes) + positional fallback.
// ============================================================================
extern "C" void kernel_launch(void* const* d_in, const int* in_sizes, int n_in,
                              void* d_out, int out_size) {
    const long long EX = 33554432LL, EW = 294912LL, EBI = 256LL,
                    EWE = 9437184LL, EBE = 8192LL;

    auto pick = [&](long long elems) -> const float* {
        for (int i = 0; i < n_in; i++) {
            long long s = (long long)in_sizes[i];
            if (s == elems || s == elems * 4) return (const float*)d_in[i];
        }
        return nullptr;
    };
    const float* X    = pick(EX);
    const float* W    = pick(EW);
    const float* bias = pick(EBI);
    const float* Werr = pick(EWE);
    const float* Berr = pick(EBE);

    if (!X || !W || !bias || !Werr || !Berr) {
        if (n_in >= 5) {
            X    = (const float*)d_in[0];
            W    = (const float*)d_in[1];
            bias = (const float*)d_in[2];
            Werr = (const float*)d_in[3];
            Berr = (const float*)d_in[4];
        } else {
            return;
        }
    }

    float* out = (float*)d_out;

    cudaFuncSetAttribute(conv_main, cudaFuncAttributeMaxDynamicSharedMemorySize,
                         (int)SMEM_TOTAL);

    prep_wfrag<<<BATCH * 9, 256>>>(W, Werr);
    conv_main<<<BATCH * 64, 128, SMEM_TOTAL>>>(X, bias, Berr, out);
}